// round 10
// baseline (speedup 1.0000x reference)
#include <cuda_runtime.h>

// Problem constants (from reference): N=32, RES=256, C=2, K=1024, T=1, EPS=1e-6
#define NB   32
#define RESO 256
#define KP   1024
#define EPSF 1e-6f
#define C1F  1.4426950408889634f          // log2(e)/T
#define UF   (C1F * C1F)                  // folded scale on squared distances
#define LN2F 0.6931471805599453f

// Scratch (no allocations allowed) --------------------------------------------
__device__ float g_sx[NB * KP];         // src.x + eps
__device__ float g_sy[NB * KP];         // src.y + eps
__device__ float g_sp[NB * KP];         // u * |src|^2
__device__ float g_part[1024];          // per-block weighted loss partials
__device__ float g_cnt [1024];          // per-block visibility counts
__device__ int   g_ctr = 0;             // last-block counter (self-resetting)

// MUFU intrinsics (abs/neg as source modifiers, folded by ptxas) --------------
__device__ __forceinline__ float lg2a(float x) { float y; asm("lg2.approx.f32 %0, %1;" : "=f"(y) : "f"(x)); return y; }
__device__ __forceinline__ float sqrt_abs(float x) {
    float y; asm("{ .reg .f32 t; abs.f32 t, %1; sqrt.approx.f32 %0, t; }" : "=f"(y) : "f"(x)); return y;
}
__device__ __forceinline__ float ex2_neg(float x) {
    float y; asm("{ .reg .f32 t; neg.f32 t, %1; ex2.approx.f32 %0, t; }" : "=f"(y) : "f"(x)); return y;
}

// Packed f32x2 helpers --------------------------------------------------------
typedef unsigned long long u64;
__device__ __forceinline__ u64 pack2(float v) {
    u64 r; asm("mov.b64 %0, {%1, %1};" : "=l"(r) : "f"(v)); return r;
}
__device__ __forceinline__ u64 add2(u64 a, u64 b) {
    u64 r; asm("add.rn.f32x2 %0, %1, %2;" : "=l"(r) : "l"(a), "l"(b)); return r;
}
__device__ __forceinline__ u64 fma2(u64 a, u64 b, u64 c) {
    u64 r; asm("fma.rn.f32x2 %0, %1, %2, %3;" : "=l"(r) : "l"(a), "l"(b), "l"(c)); return r;
}
__device__ __forceinline__ void unpack2(u64 p, float& lo, float& hi) {
    asm("mov.b64 {%0, %1}, %2;" : "=f"(lo), "=f"(hi) : "l"(p));
}

// Kernel 1: corner-parallel bilinear sampling of SRC only (SoA outputs) -------
__global__ __launch_bounds__(256) void sample_kernel(
        const float* __restrict__ sflow, const float* __restrict__ skp) {
    int g      = blockIdx.x * blockDim.x + threadIdx.x;    // [0, 131072)
    int k      = g >> 2;                                   // n*K + kp
    int corner = g & 3;
    int n      = k >> 10;

    float2 p = ((const float2*)skp)[k];
    float x0f = floorf(p.x), y0f = floorf(p.y);
    float wx  = p.x - x0f,   wy  = p.y - y0f;
    int dx = corner & 1, dy = corner >> 1;
    int xi = (int)x0f + dx, yi = (int)y0f + dy;
    float w = (dx ? wx : 1.f - wx) * (dy ? wy : 1.f - wy);

    float ax = 0.f, ay = 0.f;
    if (xi >= 0 && xi < RESO && yi >= 0 && yi < RESO) {
        const float2 v = *(const float2*)(sflow + ((((size_t)n * RESO + yi) * RESO + xi) << 1));
        ax = v.x * w;
        ay = v.y * w;
    }
    ax += __shfl_xor_sync(0xffffffffu, ax, 1);
    ay += __shfl_xor_sync(0xffffffffu, ay, 1);
    ax += __shfl_xor_sync(0xffffffffu, ax, 2);
    ay += __shfl_xor_sync(0xffffffffu, ay, 2);

    if (corner == 0) {
        float sx = ax + EPSF, sy = ay + EPSF;              // fold +eps into src side
        g_sx[k] = sx;
        g_sy[k] = sy;
        g_sp[k] = UF * fmaf(sx, sx, sy * sy);              // u*|s|^2
    }
}

// Kernel 2: inline trg sampling + pairwise + CE diag + fused reduction --------
// 1 warp = 4 consecutive j's (samples its own trg points). Block = 8 warps.
// Grid = 32 batches * 32 = 1024 blocks.
__global__ __launch_bounds__(256) void pair_kernel(
        const float* __restrict__ tflow, const float* __restrict__ tkp,
        const int* __restrict__ vis, const float* __restrict__ wt,
        float* __restrict__ out) {
    __shared__ float shx[KP], shy[KP], shp[KP];            // src SoA for batch n (12 KB)
    __shared__ float sh_l[8], sh_v[8];
    __shared__ bool  s_last;
    const int warp = threadIdx.x >> 5, lane = threadIdx.x & 31;
    const int n     = blockIdx.x >> 5;                     // 32 blocks per batch
    const int jbase = ((blockIdx.x & 31) << 5) + (warp << 2);

    {   // vectorized smem fill: 256 float4 per array
        const float4* gx = (const float4*)(g_sx + n * KP);
        const float4* gy = (const float4*)(g_sy + n * KP);
        const float4* gp = (const float4*)(g_sp + n * KP);
        ((float4*)shx)[threadIdx.x] = gx[threadIdx.x];
        ((float4*)shy)[threadIdx.x] = gy[threadIdx.x];
        ((float4*)shp)[threadIdx.x] = gp[threadIdx.x];
    }

    // Inline trg bilinear sampling: lanes 0..15, 4 lanes (corners) per j ------
    float ax = 0.f, ay = 0.f;
    if (lane < 16) {
        int q = lane >> 2, c = lane & 3;
        float2 p = ((const float2*)tkp)[n * KP + jbase + q];
        float x0f = floorf(p.x), y0f = floorf(p.y);
        float wx = p.x - x0f, wy = p.y - y0f;
        int dx = c & 1, dy = c >> 1;
        int xi = (int)x0f + dx, yi = (int)y0f + dy;
        if (xi >= 0 && xi < RESO && yi >= 0 && yi < RESO) {
            float w = (dx ? wx : 1.f - wx) * (dy ? wy : 1.f - wy);
            const float2 v = *(const float2*)(tflow + ((((size_t)n * RESO + yi) * RESO + xi) << 1));
            ax = v.x * w;
            ay = v.y * w;
        }
    }
    ax += __shfl_xor_sync(0xffffffffu, ax, 1);
    ay += __shfl_xor_sync(0xffffffffu, ay, 1);
    ax += __shfl_xor_sync(0xffffffffu, ax, 2);
    ay += __shfl_xor_sync(0xffffffffu, ay, 2);
    // lane 4q now holds trg(jbase+q); broadcast to all lanes
    u64 qx2[4], qy2[4], rr2[4];
#pragma unroll
    for (int q = 0; q < 4; q++) {
        float txq = __shfl_sync(0xffffffffu, ax, q << 2);
        float tyq = __shfl_sync(0xffffffffu, ay, q << 2);
        qx2[q] = pack2(-2.f * UF * txq);
        qy2[q] = pack2(-2.f * UF * tyq);
        rr2[q] = pack2(UF * fmaf(txq, txq, tyq * tyq));
    }
    __syncthreads();

    float a0 = 0.f, a1 = 0.f, a2 = 0.f, a3 = 0.f;
    const ulonglong2* px = (const ulonglong2*)shx;         // LDS.128: 2 packed pairs
    const ulonglong2* py = (const ulonglong2*)shy;
    const ulonglong2* pp = (const ulonglong2*)shp;
#pragma unroll
    for (int it = 0; it < KP / 4; it += 32) {              // 8 iterations
        int pi = it + lane;
        ulonglong2 X = px[pi], Y = py[pi], P = pp[pi];
#pragma unroll
        for (int h = 0; h < 2; h++) {
            u64 x2 = h ? X.y : X.x;
            u64 y2 = h ? Y.y : Y.x;
            u64 p2 = h ? P.y : P.x;
            {   u64 d = fma2(x2, qx2[0], fma2(y2, qy2[0], add2(p2, rr2[0])));
                float lo, hi; unpack2(d, lo, hi);
                a0 += ex2_neg(sqrt_abs(lo));
                a0 += ex2_neg(sqrt_abs(hi)); }
            {   u64 d = fma2(x2, qx2[1], fma2(y2, qy2[1], add2(p2, rr2[1])));
                float lo, hi; unpack2(d, lo, hi);
                a1 += ex2_neg(sqrt_abs(lo));
                a1 += ex2_neg(sqrt_abs(hi)); }
            {   u64 d = fma2(x2, qx2[2], fma2(y2, qy2[2], add2(p2, rr2[2])));
                float lo, hi; unpack2(d, lo, hi);
                a2 += ex2_neg(sqrt_abs(lo));
                a2 += ex2_neg(sqrt_abs(hi)); }
            {   u64 d = fma2(x2, qx2[3], fma2(y2, qy2[3], add2(p2, rr2[3])));
                float lo, hi; unpack2(d, lo, hi);
                a3 += ex2_neg(sqrt_abs(lo));
                a3 += ex2_neg(sqrt_abs(hi)); }
        }
    }
#pragma unroll
    for (int o = 16; o; o >>= 1) {
        a0 += __shfl_xor_sync(0xffffffffu, a0, o);
        a1 += __shfl_xor_sync(0xffffffffu, a1, o);
        a2 += __shfl_xor_sync(0xffffffffu, a2, o);
        a3 += __shfl_xor_sync(0xffffffffu, a3, o);
    }

    if (lane == 0) {
        float acc[4] = {a0, a1, a2, a3};
        float lsum = 0.f, vsum = 0.f;
#pragma unroll
        for (int q = 0; q < 4; q++) {
            int j = jbase + q;
            float qx, qy, rrv, dum;
            unpack2(qx2[q], qx, dum);
            unpack2(qy2[q], qy, dum);
            unpack2(rr2[q], rrv, dum);
            // scaled diagonal: v_jj = C1 * dist_jj (same dot form)
            float dsq = fmaf(shx[j], qx, fmaf(shy[j], qy, shp[j] + rrv));
            float vjj = sqrt_abs(dsq);
            // loss = 2*(ln(acc) + dist_jj) = 2*ln2*(lg2(acc) + v_jj)
            float loss = (2.f * LN2F) * (lg2a(acc[q]) + vjj);
            float vi = vis[n * KP + j] ? 1.f : 0.f;
            lsum = fmaf(loss * wt[n * KP + j], vi, lsum);
            vsum += vi;
        }
        sh_l[warp] = lsum; sh_v[warp] = vsum;
    }
    __syncthreads();

    if (threadIdx.x == 0) {
        float l = 0.f, v = 0.f;
#pragma unroll
        for (int w = 0; w < 8; w++) { l += sh_l[w]; v += sh_v[w]; }
        g_part[blockIdx.x] = l;
        g_cnt [blockIdx.x] = v;
        __threadfence();
        int prev = atomicAdd(&g_ctr, 1);
        s_last = (prev == 1023);
    }
    __syncthreads();

    // Last block performs the final deterministic fixed-tree reduce.
    if (s_last) {
        __shared__ float fl[8], fv[8];
        float l = 0.f, v = 0.f;
#pragma unroll
        for (int r = 0; r < 4; r++) {
            int i = threadIdx.x + (r << 8);
            l += g_part[i];
            v += g_cnt [i];
        }
#pragma unroll
        for (int o = 16; o; o >>= 1) {
            l += __shfl_xor_sync(0xffffffffu, l, o);
            v += __shfl_xor_sync(0xffffffffu, v, o);
        }
        if (lane == 0) { fl[warp] = l; fv[warp] = v; }
        __syncthreads();
        if (threadIdx.x == 0) {
            l = 0.f; v = 0.f;
#pragma unroll
            for (int w = 0; w < 8; w++) { l += fl[w]; v += fv[w]; }
            out[0] = l / v;
            g_ctr = 0;                                     // reset for next graph replay
        }
    }
}

extern "C" void kernel_launch(void* const* d_in, const int* in_sizes, int n_in,
                              void* d_out, int out_size) {
    const float* sflow = (const float*)d_in[0];
    const float* tflow = (const float*)d_in[1];
    const float* skp   = (const float*)d_in[2];
    const float* tkp   = (const float*)d_in[3];
    const int*   vis   = (const int*)d_in[4];   // bool serialized as int32
    const float* wt    = (const float*)d_in[5];
    float*       out   = (float*)d_out;

    sample_kernel<<<(NB * KP * 4) / 256, 256>>>(sflow, skp);
    pair_kernel<<<1024, 256>>>(tflow, tkp, vis, wt, out);
}